// round 1
// baseline (speedup 1.0000x reference)
#include <cuda_runtime.h>
#include <math.h>

static constexpr int B_ = 4, T_ = 2048, D_ = 1024, H_ = 16, HD_ = 64;
static constexpr int M_ = B_ * T_;   // 8192 rows

// ---- scratch (static __device__ arrays; no allocation) ----
__device__ float g_h[M_ * D_];        // ln output (reused for ln1 and ln2)
__device__ float g_q[M_ * D_];
__device__ float g_k[M_ * D_];
__device__ float g_v[M_ * D_];
__device__ float g_attn[M_ * D_];
__device__ float g_x1[M_ * D_];       // x + attn@Wo + bo
__device__ float g_ff[M_ * 4 * D_];   // FFN hidden

// ======================= LayerNorm =======================
__global__ __launch_bounds__(256) void ln_kernel(
    const float* __restrict__ x, const float* __restrict__ gamma,
    const float* __restrict__ beta, float* __restrict__ out)
{
    int row = blockIdx.x;
    const float* xr = x + (size_t)row * D_;
    float* orow = out + (size_t)row * D_;
    int t = threadIdx.x;
    float v[4];
    float s = 0.f, s2 = 0.f;
#pragma unroll
    for (int i = 0; i < 4; i++) {
        float val = xr[t + i * 256];
        v[i] = val; s += val; s2 += val * val;
    }
#pragma unroll
    for (int o = 16; o; o >>= 1) {
        s  += __shfl_xor_sync(0xffffffffu, s, o);
        s2 += __shfl_xor_sync(0xffffffffu, s2, o);
    }
    __shared__ float red[16];
    if ((t & 31) == 0) { red[t >> 5] = s; red[8 + (t >> 5)] = s2; }
    __syncthreads();
    float ts = 0.f, ts2 = 0.f;
#pragma unroll
    for (int w = 0; w < 8; w++) { ts += red[w]; ts2 += red[8 + w]; }
    float mean = ts * (1.f / D_);
    float var  = ts2 * (1.f / D_) - mean * mean;
    float inv  = rsqrtf(var + 1e-5f);
#pragma unroll
    for (int i = 0; i < 4; i++) {
        int c = t + i * 256;
        orow[c] = gamma[c] * (v[i] - mean) * inv + beta[c];
    }
}

// ======================= GEMM: C = A@W (+bias)(+resid)(gelu?) ============
__device__ __forceinline__ float gelu_f(float x) {
    float u = 0.7978845608028654f * (x + 0.044715f * x * x * x);
    return 0.5f * x * (1.f + tanhf(u));
}

// 128x64 block tile, BK=16, 256 threads, 8x4 per thread
__global__ __launch_bounds__(256) void gemm_kernel(
    const float* __restrict__ A, const float* __restrict__ W,
    const float* __restrict__ bias, const float* __restrict__ resid,
    float* __restrict__ C, int M, int N, int K, int act)
{
    __shared__ float As[16][132];   // [k][m], padded
    __shared__ float Bs[16][68];    // [k][n], padded

    int tid = threadIdx.x;
    int bm = blockIdx.y * 128;
    int bn = blockIdx.x * 64;
    int ty = tid >> 4, tx = tid & 15;

    int arow = tid >> 1;            // 0..127
    int acol = (tid & 1) * 8;       // 0 or 8
    int brow = tid >> 4;            // 0..15
    int bcol = (tid & 15) * 4;      // 0..60

    const float* Ag = A + (size_t)(bm + arow) * K + acol;
    const float* Wg = W + (size_t)brow * N + bn + bcol;

    float acc[8][4];
#pragma unroll
    for (int i = 0; i < 8; i++)
#pragma unroll
        for (int j = 0; j < 4; j++) acc[i][j] = 0.f;

    for (int k0 = 0; k0 < K; k0 += 16) {
        float4 a0 = *(const float4*)Ag;
        float4 a1 = *(const float4*)(Ag + 4);
        float4 b0 = *(const float4*)Wg;
        As[acol + 0][arow] = a0.x; As[acol + 1][arow] = a0.y;
        As[acol + 2][arow] = a0.z; As[acol + 3][arow] = a0.w;
        As[acol + 4][arow] = a1.x; As[acol + 5][arow] = a1.y;
        As[acol + 6][arow] = a1.z; As[acol + 7][arow] = a1.w;
        *(float4*)&Bs[brow][bcol] = b0;
        __syncthreads();
#pragma unroll
        for (int kk = 0; kk < 16; kk++) {
            float4 a0v = *(const float4*)&As[kk][ty * 8];
            float4 a1v = *(const float4*)&As[kk][ty * 8 + 4];
            float4 bv  = *(const float4*)&Bs[kk][tx * 4];
            float av[8] = {a0v.x, a0v.y, a0v.z, a0v.w, a1v.x, a1v.y, a1v.z, a1v.w};
            float bb[4] = {bv.x, bv.y, bv.z, bv.w};
#pragma unroll
            for (int i = 0; i < 8; i++)
#pragma unroll
                for (int j = 0; j < 4; j++)
                    acc[i][j] = fmaf(av[i], bb[j], acc[i][j]);
        }
        __syncthreads();
        Ag += 16;
        Wg += (size_t)16 * N;
    }

    float bi[4];
#pragma unroll
    for (int j = 0; j < 4; j++) bi[j] = bias ? bias[bn + tx * 4 + j] : 0.f;
#pragma unroll
    for (int i = 0; i < 8; i++) {
        size_t roff = (size_t)(bm + ty * 8 + i) * N + bn + tx * 4;
#pragma unroll
        for (int j = 0; j < 4; j++) {
            float val = acc[i][j] + bi[j];
            if (resid) val += resid[roff + j];
            if (act) val = gelu_f(val);
            C[roff + j] = val;
        }
    }
}

// ======================= Causal flash attention ==========================
// One block per (query-tile 64, b*h). 256 threads. HD=64, scale=0.125.
__global__ __launch_bounds__(256) void flash_kernel(
    const float* __restrict__ Qg, const float* __restrict__ Kg,
    const float* __restrict__ Vg, float* __restrict__ Og)
{
    extern __shared__ float sm[];
    float (*Qs)[68] = (float(*)[68])(sm);             // [d][row]
    float (*Ks)[68] = (float(*)[68])(sm + 4352);      // [d][j]
    float (*Vs)[68] = (float(*)[68])(sm + 2 * 4352);  // [j][d]
    float (*PT)[68] = (float(*)[68])(sm + 3 * 4352);  // [j][row]
    float (*Ss)[68] = (float(*)[68])(sm + 4 * 4352);  // [row][j]
    float* m_s     = sm + 5 * 4352;
    float* l_s     = m_s + 64;
    float* alpha_s = l_s + 64;

    int qt = blockIdx.x, bh = blockIdx.y;
    int b = bh >> 4, h = bh & 15;
    int tid = threadIdx.x;
    int ty = tid >> 4, tx = tid & 15;
    const size_t base = (size_t)b * T_ * D_ + (size_t)h * HD_;

    int lr  = tid >> 2;          // 0..63
    int ldc = (tid & 3) * 16;    // 0,16,32,48
    {
        const float* qp = Qg + base + (size_t)(qt * 64 + lr) * D_ + ldc;
#pragma unroll
        for (int c = 0; c < 16; c += 4) {
            float4 v = *(const float4*)(qp + c);
            Qs[ldc + c + 0][lr] = v.x; Qs[ldc + c + 1][lr] = v.y;
            Qs[ldc + c + 2][lr] = v.z; Qs[ldc + c + 3][lr] = v.w;
        }
    }
    if (tid < 64) { m_s[tid] = -INFINITY; l_s[tid] = 0.f; }

    float acc[4][4];
#pragma unroll
    for (int i = 0; i < 4; i++)
#pragma unroll
        for (int j = 0; j < 4; j++) acc[i][j] = 0.f;

    for (int kt = 0; kt <= qt; kt++) {
        __syncthreads();   // protect Ks/Vs/PT from previous iteration readers
        {
            const float* kp = Kg + base + (size_t)(kt * 64 + lr) * D_ + ldc;
            const float* vp = Vg + base + (size_t)(kt * 64 + lr) * D_ + ldc;
#pragma unroll
            for (int c = 0; c < 16; c += 4) {
                float4 kv = *(const float4*)(kp + c);
                Ks[ldc + c + 0][lr] = kv.x; Ks[ldc + c + 1][lr] = kv.y;
                Ks[ldc + c + 2][lr] = kv.z; Ks[ldc + c + 3][lr] = kv.w;
                float4 vv = *(const float4*)(vp + c);
                *(float4*)&Vs[lr][ldc + c] = vv;
            }
        }
        __syncthreads();

        // S = (Q @ K^T) * scale   -- GEMM-style 4x4 register tile
        float sa[4][4];
#pragma unroll
        for (int i = 0; i < 4; i++)
#pragma unroll
            for (int j = 0; j < 4; j++) sa[i][j] = 0.f;
#pragma unroll 8
        for (int kk = 0; kk < 64; kk++) {
            float4 av = *(const float4*)&Qs[kk][ty * 4];
            float4 bv = *(const float4*)&Ks[kk][tx * 4];
            float aa[4] = {av.x, av.y, av.z, av.w};
            float bb[4] = {bv.x, bv.y, bv.z, bv.w};
#pragma unroll
            for (int i = 0; i < 4; i++)
#pragma unroll
                for (int j = 0; j < 4; j++)
                    sa[i][j] = fmaf(aa[i], bb[j], sa[i][j]);
        }
#pragma unroll
        for (int i = 0; i < 4; i++) {
            float4 s4 = make_float4(sa[i][0] * 0.125f, sa[i][1] * 0.125f,
                                    sa[i][2] * 0.125f, sa[i][3] * 0.125f);
            *(float4*)&Ss[ty * 4 + i][tx * 4] = s4;
        }
        __syncthreads();

        // online softmax stats: thread (row, sub) handles 16 of 64 columns
        {
            int row = tid >> 2, sub = tid & 3;
            int jb = sub * 16;
            bool diag = (kt == qt);
            float sv[16];
            float mloc = -INFINITY;
#pragma unroll
            for (int jj = 0; jj < 16; jj++) {
                float s = Ss[row][jb + jj];
                if (diag && (jb + jj) > row) s = -INFINITY;
                sv[jj] = s;
                mloc = fmaxf(mloc, s);
            }
            mloc = fmaxf(mloc, __shfl_xor_sync(0xffffffffu, mloc, 1));
            mloc = fmaxf(mloc, __shfl_xor_sync(0xffffffffu, mloc, 2));
            float m_old = m_s[row];
            float m_new = fmaxf(m_old, mloc);
            float ps = 0.f;
#pragma unroll
            for (int jj = 0; jj < 16; jj++) {
                float p = (sv[jj] == -INFINITY) ? 0.f : __expf(sv[jj] - m_new);
                PT[jb + jj][row] = p;
                ps += p;
            }
            ps += __shfl_xor_sync(0xffffffffu, ps, 1);
            ps += __shfl_xor_sync(0xffffffffu, ps, 2);
            if (sub == 0) {
                float alpha = (m_old == -INFINITY) ? 0.f : __expf(m_old - m_new);
                alpha_s[row] = alpha;
                l_s[row] = l_s[row] * alpha + ps;
                m_s[row] = m_new;
            }
        }
        __syncthreads();

        // rescale accumulator + O += P @ V
        float al[4];
#pragma unroll
        for (int i = 0; i < 4; i++) al[i] = alpha_s[ty * 4 + i];
#pragma unroll
        for (int i = 0; i < 4; i++)
#pragma unroll
            for (int j = 0; j < 4; j++) acc[i][j] *= al[i];
#pragma unroll 8
        for (int j = 0; j < 64; j++) {
            float4 pv = *(const float4*)&PT[j][ty * 4];
            float4 vv = *(const float4*)&Vs[j][tx * 4];
            float pp[4] = {pv.x, pv.y, pv.z, pv.w};
            float bb[4] = {vv.x, vv.y, vv.z, vv.w};
#pragma unroll
            for (int i = 0; i < 4; i++)
#pragma unroll
                for (int jj = 0; jj < 4; jj++)
                    acc[i][jj] = fmaf(pp[i], bb[jj], acc[i][jj]);
        }
    }
    __syncthreads();

    float inv[4];
#pragma unroll
    for (int i = 0; i < 4; i++) inv[i] = 1.f / l_s[ty * 4 + i];
#pragma unroll
    for (int i = 0; i < 4; i++) {
        float* op = Og + base + (size_t)(qt * 64 + ty * 4 + i) * D_ + tx * 4;
        float4 o4 = make_float4(acc[i][0] * inv[i], acc[i][1] * inv[i],
                                acc[i][2] * inv[i], acc[i][3] * inv[i]);
        *(float4*)op = o4;
    }
}

// ======================= launch ==========================================
extern "C" void kernel_launch(void* const* d_in, const int* in_sizes, int n_in,
                              void* d_out, int out_size)
{
    const float* x      = (const float*)d_in[0];
    const float* Wq     = (const float*)d_in[1];
    const float* Wk     = (const float*)d_in[2];
    const float* Wv     = (const float*)d_in[3];
    const float* Wo     = (const float*)d_in[4];
    const float* bo     = (const float*)d_in[5];
    const float* W1     = (const float*)d_in[6];
    const float* b1     = (const float*)d_in[7];
    const float* W2     = (const float*)d_in[8];
    const float* b2     = (const float*)d_in[9];
    const float* gamma1 = (const float*)d_in[10];
    const float* beta1  = (const float*)d_in[11];
    const float* gamma2 = (const float*)d_in[12];
    const float* beta2  = (const float*)d_in[13];
    float* out = (float*)d_out;

    float *h, *q, *k, *v, *attn, *x1, *ff;
    cudaGetSymbolAddress((void**)&h,    g_h);
    cudaGetSymbolAddress((void**)&q,    g_q);
    cudaGetSymbolAddress((void**)&k,    g_k);
    cudaGetSymbolAddress((void**)&v,    g_v);
    cudaGetSymbolAddress((void**)&attn, g_attn);
    cudaGetSymbolAddress((void**)&x1,   g_x1);
    cudaGetSymbolAddress((void**)&ff,   g_ff);

    // LN1
    ln_kernel<<<M_, 256>>>(x, gamma1, beta1, h);

    // QKV projections
    dim3 gD(D_ / 64, M_ / 128);
    gemm_kernel<<<gD, 256>>>(h, Wq, nullptr, nullptr, q, M_, D_, D_, 0);
    gemm_kernel<<<gD, 256>>>(h, Wk, nullptr, nullptr, k, M_, D_, D_, 0);
    gemm_kernel<<<gD, 256>>>(h, Wv, nullptr, nullptr, v, M_, D_, D_, 0);

    // causal attention
    const int FLASH_SMEM = (5 * 4352 + 192) * (int)sizeof(float);
    cudaFuncSetAttribute(flash_kernel, cudaFuncAttributeMaxDynamicSharedMemorySize, FLASH_SMEM);
    dim3 gf(T_ / 64, B_ * H_);
    flash_kernel<<<gf, 256, FLASH_SMEM>>>(q, k, v, attn);

    // output projection + residual
    gemm_kernel<<<gD, 256>>>(attn, Wo, bo, x, x1, M_, D_, D_, 0);

    // LN2
    ln_kernel<<<M_, 256>>>(x1, gamma2, beta2, h);

    // FFN
    dim3 gU(4 * D_ / 64, M_ / 128);
    gemm_kernel<<<gU, 256>>>(h, W1, b1, nullptr, ff, M_, 4 * D_, D_, 1);
    gemm_kernel<<<gD, 256>>>(ff, W2, b2, x1, out, M_, D_, 4 * D_, 0);
}

// round 2
// speedup vs baseline: 1.4637x; 1.4637x over previous
#include <cuda_runtime.h>
#include <math.h>
#include <stdint.h>

static constexpr int B_ = 4, T_ = 2048, D_ = 1024, H_ = 16, HD_ = 64;
static constexpr int M_ = B_ * T_;   // 8192 rows

// ---- scratch (static __device__ arrays; no allocation) ----
__device__ float g_h[M_ * D_];        // ln output (reused for ln1 and ln2)
__device__ float g_q[M_ * D_];
__device__ float g_k[M_ * D_];
__device__ float g_v[M_ * D_];
__device__ float g_attn[M_ * D_];
__device__ float g_x1[M_ * D_];       // x + attn@Wo + bo
__device__ float g_ff[M_ * 4 * D_];   // FFN hidden

// ======================= LayerNorm =======================
__global__ __launch_bounds__(256) void ln_kernel(
    const float* __restrict__ x, const float* __restrict__ gamma,
    const float* __restrict__ beta, float* __restrict__ out)
{
    int row = blockIdx.x;
    const float* xr = x + (size_t)row * D_;
    float* orow = out + (size_t)row * D_;
    int t = threadIdx.x;
    float v[4];
    float s = 0.f, s2 = 0.f;
#pragma unroll
    for (int i = 0; i < 4; i++) {
        float val = xr[t + i * 256];
        v[i] = val; s += val; s2 += val * val;
    }
#pragma unroll
    for (int o = 16; o; o >>= 1) {
        s  += __shfl_xor_sync(0xffffffffu, s, o);
        s2 += __shfl_xor_sync(0xffffffffu, s2, o);
    }
    __shared__ float red[16];
    if ((t & 31) == 0) { red[t >> 5] = s; red[8 + (t >> 5)] = s2; }
    __syncthreads();
    float ts = 0.f, ts2 = 0.f;
#pragma unroll
    for (int w = 0; w < 8; w++) { ts += red[w]; ts2 += red[8 + w]; }
    float mean = ts * (1.f / D_);
    float var  = ts2 * (1.f / D_) - mean * mean;
    float inv  = rsqrtf(var + 1e-5f);
#pragma unroll
    for (int i = 0; i < 4; i++) {
        int c = t + i * 256;
        orow[c] = gamma[c] * (v[i] - mean) * inv + beta[c];
    }
}

// ======================= tf32 tensor-core GEMM ===========================
__device__ __forceinline__ float gelu_f(float x) {
    float u = 0.7978845608028654f * (x + 0.044715f * x * x * x);
    return 0.5f * x * (1.f + tanhf(u));
}

__device__ __forceinline__ float tf32r(float x) {
    uint32_t u;
    asm("cvt.rna.tf32.f32 %0, %1;" : "=r"(u) : "f"(x));
    return __uint_as_float(u);
}

__device__ __forceinline__ void mma_tf32(float* d, const uint32_t* a, const uint32_t* b) {
    asm volatile(
        "mma.sync.aligned.m16n8k8.row.col.f32.tf32.tf32.f32 "
        "{%0,%1,%2,%3}, {%4,%5,%6,%7}, {%8,%9}, {%0,%1,%2,%3};"
        : "+f"(d[0]), "+f"(d[1]), "+f"(d[2]), "+f"(d[3])
        : "r"(a[0]), "r"(a[1]), "r"(a[2]), "r"(a[3]), "r"(b[0]), "r"(b[1]));
}

// C = A[M,K] @ W[K,N] (+bias)(+resid)(gelu?)
// 128x128 block tile, BK=16, 256 threads = 8 warps (4 in M x 2 in N),
// warp tile 32x64, mma m16n8k8 tf32.
// smem stores tf32-rounded values with k permuted so that the (k, k+4)
// fragment pairs are adjacent -> LDS.64 frag loads at the 2-cycle floor.
__global__ __launch_bounds__(256) void gemm_tf32_kernel(
    const float* __restrict__ A, const float* __restrict__ W,
    const float* __restrict__ bias, const float* __restrict__ resid,
    float* __restrict__ C, int M, int N, int K, int act)
{
    __shared__ float As[128][20];   // [m][k_phys], stride 20 -> conflict-floor
    __shared__ float Bs[128][20];   // [n][k_phys]

    int tid = threadIdx.x;
    int bm = blockIdx.y * 128;
    int bn = blockIdx.x * 128;
    int warp = tid >> 5, lane = tid & 31;
    int wm = warp & 3;          // 0..3  (M)
    int wn = warp >> 2;         // 0..1  (N)
    int gr = lane >> 2;         // groupID 0..7
    int gc = lane & 3;          // threadID_in_group 0..3

    // global-load indices
    int ar  = tid >> 2;         // A rows ar, ar+64
    int ac4 = tid & 3;          // A col group: k = ac4*4 .. +3
    int bkr = tid >> 4;         // B row (k) 0..15
    int bc4 = tid & 15;         // B cols bc4*4 (+0, +64)

    float acc[2][8][4];
#pragma unroll
    for (int i = 0; i < 2; i++)
#pragma unroll
        for (int j = 0; j < 8; j++)
#pragma unroll
            for (int c = 0; c < 4; c++) acc[i][j][c] = 0.f;

    // phys k for B store (row bkr): (k&3)*2 + ((k&7)>>2) + 8*(k>>3)
    int bpk = (bkr & 3) * 2 + ((bkr & 7) >> 2) + 8 * (bkr >> 3);
    // phys base for A store of elements k=ac4*4+e : 2e + (ac4&1) + 8*(ac4>>1)
    int apb = (ac4 & 1) + 8 * (ac4 >> 1);

    for (int k0 = 0; k0 < K; k0 += 16) {
        // ---- load A tile (128x16) ----
#pragma unroll
        for (int h = 0; h < 2; h++) {
            int row = ar + h * 64;
            float4 v = *(const float4*)(A + (size_t)(bm + row) * K + k0 + ac4 * 4);
            As[row][apb + 0] = tf32r(v.x);
            As[row][apb + 2] = tf32r(v.y);
            As[row][apb + 4] = tf32r(v.z);
            As[row][apb + 6] = tf32r(v.w);
        }
        // ---- load B tile (16x128), store transposed ----
#pragma unroll
        for (int h = 0; h < 2; h++) {
            int col = bc4 * 4 + h * 64;
            float4 v = *(const float4*)(W + (size_t)(k0 + bkr) * N + bn + col);
            Bs[col + 0][bpk] = tf32r(v.x);
            Bs[col + 1][bpk] = tf32r(v.y);
            Bs[col + 2][bpk] = tf32r(v.z);
            Bs[col + 3][bpk] = tf32r(v.w);
        }
        __syncthreads();

#pragma unroll
        for (int ks = 0; ks < 2; ks++) {
            int kb = ks * 8;
            uint32_t af[2][4];
#pragma unroll
            for (int i = 0; i < 2; i++) {
                int m = wm * 32 + i * 16 + gr;
                float2 a02 = *(const float2*)&As[m][kb + 2 * gc];
                float2 a13 = *(const float2*)&As[m + 8][kb + 2 * gc];
                af[i][0] = __float_as_uint(a02.x);
                af[i][2] = __float_as_uint(a02.y);
                af[i][1] = __float_as_uint(a13.x);
                af[i][3] = __float_as_uint(a13.y);
            }
#pragma unroll
            for (int j = 0; j < 8; j++) {
                int n = wn * 64 + j * 8 + gr;
                float2 b01 = *(const float2*)&Bs[n][kb + 2 * gc];
                uint32_t bf[2] = {__float_as_uint(b01.x), __float_as_uint(b01.y)};
                mma_tf32(acc[0][j], af[0], bf);
                mma_tf32(acc[1][j], af[1], bf);
            }
        }
        __syncthreads();
    }

    // ---- epilogue ----
#pragma unroll
    for (int i = 0; i < 2; i++) {
#pragma unroll
        for (int j = 0; j < 8; j++) {
            int row = bm + wm * 32 + i * 16 + gr;
            int col = bn + wn * 64 + j * 8 + 2 * gc;
            float b0 = bias ? bias[col]     : 0.f;
            float b1 = bias ? bias[col + 1] : 0.f;
#pragma unroll
            for (int hh = 0; hh < 2; hh++) {
                int r = row + hh * 8;
                size_t off = (size_t)r * N + col;
                float v0 = acc[i][j][2 * hh + 0] + b0;
                float v1 = acc[i][j][2 * hh + 1] + b1;
                if (resid) { v0 += resid[off]; v1 += resid[off + 1]; }
                if (act) { v0 = gelu_f(v0); v1 = gelu_f(v1); }
                float2 o = make_float2(v0, v1);
                *(float2*)(C + off) = o;
            }
        }
    }
}

// ======================= Causal flash attention ==========================
// One block per (query-tile 64, b*h). 256 threads. HD=64, scale=0.125.
__global__ __launch_bounds__(256) void flash_kernel(
    const float* __restrict__ Qg, const float* __restrict__ Kg,
    const float* __restrict__ Vg, float* __restrict__ Og)
{
    extern __shared__ float sm[];
    float (*Qs)[68] = (float(*)[68])(sm);             // [d][row]
    float (*Ks)[68] = (float(*)[68])(sm + 4352);      // [d][j]
    float (*Vs)[68] = (float(*)[68])(sm + 2 * 4352);  // [j][d]
    float (*PT)[68] = (float(*)[68])(sm + 3 * 4352);  // [j][row]
    float (*Ss)[68] = (float(*)[68])(sm + 4 * 4352);  // [row][j]
    float* m_s     = sm + 5 * 4352;
    float* l_s     = m_s + 64;
    float* alpha_s = l_s + 64;

    int qt = blockIdx.x, bh = blockIdx.y;
    int b = bh >> 4, h = bh & 15;
    int tid = threadIdx.x;
    int ty = tid >> 4, tx = tid & 15;
    const size_t base = (size_t)b * T_ * D_ + (size_t)h * HD_;

    int lr  = tid >> 2;          // 0..63
    int ldc = (tid & 3) * 16;    // 0,16,32,48
    {
        const float* qp = Qg + base + (size_t)(qt * 64 + lr) * D_ + ldc;
#pragma unroll
        for (int c = 0; c < 16; c += 4) {
            float4 v = *(const float4*)(qp + c);
            Qs[ldc + c + 0][lr] = v.x; Qs[ldc + c + 1][lr] = v.y;
            Qs[ldc + c + 2][lr] = v.z; Qs[ldc + c + 3][lr] = v.w;
        }
    }
    if (tid < 64) { m_s[tid] = -INFINITY; l_s[tid] = 0.f; }

    float acc[4][4];
#pragma unroll
    for (int i = 0; i < 4; i++)
#pragma unroll
        for (int j = 0; j < 4; j++) acc[i][j] = 0.f;

    for (int kt = 0; kt <= qt; kt++) {
        __syncthreads();   // protect Ks/Vs/PT from previous iteration readers
        {
            const float* kp = Kg + base + (size_t)(kt * 64 + lr) * D_ + ldc;
            const float* vp = Vg + base + (size_t)(kt * 64 + lr) * D_ + ldc;
#pragma unroll
            for (int c = 0; c < 16; c += 4) {
                float4 kv = *(const float4*)(kp + c);
                Ks[ldc + c + 0][lr] = kv.x; Ks[ldc + c + 1][lr] = kv.y;
                Ks[ldc + c + 2][lr] = kv.z; Ks[ldc + c + 3][lr] = kv.w;
                float4 vv = *(const float4*)(vp + c);
                *(float4*)&Vs[lr][ldc + c] = vv;
            }
        }
        __syncthreads();

        // S = (Q @ K^T) * scale   -- GEMM-style 4x4 register tile
        float sa[4][4];
#pragma unroll
        for (int i = 0; i < 4; i++)
#pragma unroll
            for (int j = 0; j < 4; j++) sa[i][j] = 0.f;
#pragma unroll 8
        for (int kk = 0; kk < 64; kk++) {
            float4 av = *(const float4*)&Qs[kk][ty * 4];
            float4 bv = *(const float4*)&Ks[kk][tx * 4];
            float aa[4] = {av.x, av.y, av.z, av.w};
            float bb[4] = {bv.x, bv.y, bv.z, bv.w};
#pragma unroll
            for (int i = 0; i < 4; i++)
#pragma unroll
                for (int j = 0; j < 4; j++)
                    sa[i][j] = fmaf(aa[i], bb[j], sa[i][j]);
        }
#pragma unroll
        for (int i = 0; i < 4; i++) {
            float4 s4 = make_float4(sa[i][0] * 0.125f, sa[i][1] * 0.125f,
                                    sa[i][2] * 0.125f, sa[i][3] * 0.125f);
            *(float4*)&Ss[ty * 4 + i][tx * 4] = s4;
        }
        __syncthreads();

        // online softmax stats: thread (row, sub) handles 16 of 64 columns
        {
            int row = tid >> 2, sub = tid & 3;
            int jb = sub * 16;
            bool diag = (kt == qt);
            float sv[16];
            float mloc = -INFINITY;
#pragma unroll
            for (int jj = 0; jj < 16; jj++) {
                float s = Ss[row][jb + jj];
                if (diag && (jb + jj) > row) s = -INFINITY;
                sv[jj] = s;
                mloc = fmaxf(mloc, s);
            }
            mloc = fmaxf(mloc, __shfl_xor_sync(0xffffffffu, mloc, 1));
            mloc = fmaxf(mloc, __shfl_xor_sync(0xffffffffu, mloc, 2));
            float m_old = m_s[row];
            float m_new = fmaxf(m_old, mloc);
            float ps = 0.f;
#pragma unroll
            for (int jj = 0; jj < 16; jj++) {
                float p = (sv[jj] == -INFINITY) ? 0.f : __expf(sv[jj] - m_new);
                PT[jb + jj][row] = p;
                ps += p;
            }
            ps += __shfl_xor_sync(0xffffffffu, ps, 1);
            ps += __shfl_xor_sync(0xffffffffu, ps, 2);
            if (sub == 0) {
                float alpha = (m_old == -INFINITY) ? 0.f : __expf(m_old - m_new);
                alpha_s[row] = alpha;
                l_s[row] = l_s[row] * alpha + ps;
                m_s[row] = m_new;
            }
        }
        __syncthreads();

        // rescale accumulator + O += P @ V
        float al[4];
#pragma unroll
        for (int i = 0; i < 4; i++) al[i] = alpha_s[ty * 4 + i];
#pragma unroll
        for (int i = 0; i < 4; i++)
#pragma unroll
            for (int j = 0; j < 4; j++) acc[i][j] *= al[i];
#pragma unroll 8
        for (int j = 0; j < 64; j++) {
            float4 pv = *(const float4*)&PT[j][ty * 4];
            float4 vv = *(const float4*)&Vs[j][tx * 4];
            float pp[4] = {pv.x, pv.y, pv.z, pv.w};
            float bb[4] = {vv.x, vv.y, vv.z, vv.w};
#pragma unroll
            for (int i = 0; i < 4; i++)
#pragma unroll
                for (int jj = 0; jj < 4; jj++)
                    acc[i][jj] = fmaf(pp[i], bb[jj], acc[i][jj]);
        }
    }
    __syncthreads();

    float inv[4];
#pragma unroll
    for (int i = 0; i < 4; i++) inv[i] = 1.f / l_s[ty * 4 + i];
#pragma unroll
    for (int i = 0; i < 4; i++) {
        float* op = Og + base + (size_t)(qt * 64 + ty * 4 + i) * D_ + tx * 4;
        float4 o4 = make_float4(acc[i][0] * inv[i], acc[i][1] * inv[i],
                                acc[i][2] * inv[i], acc[i][3] * inv[i]);
        *(float4*)op = o4;
    }
}

// ======================= launch ==========================================
extern "C" void kernel_launch(void* const* d_in, const int* in_sizes, int n_in,
                              void* d_out, int out_size)
{
    const float* x      = (const float*)d_in[0];
    const float* Wq     = (const float*)d_in[1];
    const float* Wk     = (const float*)d_in[2];
    const float* Wv     = (const float*)d_in[3];
    const float* Wo     = (const float*)d_in[4];
    const float* bo     = (const float*)d_in[5];
    const float* W1     = (const float*)d_in[6];
    const float* b1     = (const float*)d_in[7];
    const float* W2     = (const float*)d_in[8];
    const float* b2     = (const float*)d_in[9];
    const float* gamma1 = (const float*)d_in[10];
    const float* beta1  = (const float*)d_in[11];
    const float* gamma2 = (const float*)d_in[12];
    const float* beta2  = (const float*)d_in[13];
    float* out = (float*)d_out;

    float *h, *q, *k, *v, *attn, *x1, *ff;
    cudaGetSymbolAddress((void**)&h,    g_h);
    cudaGetSymbolAddress((void**)&q,    g_q);
    cudaGetSymbolAddress((void**)&k,    g_k);
    cudaGetSymbolAddress((void**)&v,    g_v);
    cudaGetSymbolAddress((void**)&attn, g_attn);
    cudaGetSymbolAddress((void**)&x1,   g_x1);
    cudaGetSymbolAddress((void**)&ff,   g_ff);

    // LN1
    ln_kernel<<<M_, 256>>>(x, gamma1, beta1, h);

    // QKV projections (tf32 tensor cores)
    dim3 gD(D_ / 128, M_ / 128);
    gemm_tf32_kernel<<<gD, 256>>>(h, Wq, nullptr, nullptr, q, M_, D_, D_, 0);
    gemm_tf32_kernel<<<gD, 256>>>(h, Wk, nullptr, nullptr, k, M_, D_, D_, 0);
    gemm_tf32_kernel<<<gD, 256>>>(h, Wv, nullptr, nullptr, v, M_, D_, D_, 0);

    // causal attention
    const int FLASH_SMEM = (5 * 4352 + 192) * (int)sizeof(float);
    cudaFuncSetAttribute(flash_kernel, cudaFuncAttributeMaxDynamicSharedMemorySize, FLASH_SMEM);
    dim3 gf(T_ / 64, B_ * H_);
    flash_kernel<<<gf, 256, FLASH_SMEM>>>(q, k, v, attn);

    // output projection + residual
    gemm_tf32_kernel<<<gD, 256>>>(attn, Wo, bo, x, x1, M_, D_, D_, 0);

    // LN2
    ln_kernel<<<M_, 256>>>(x1, gamma2, beta2, h);

    // FFN
    dim3 gU(4 * D_ / 128, M_ / 128);
    gemm_tf32_kernel<<<gU, 256>>>(h, W1, b1, nullptr, ff, M_, 4 * D_, D_, 1);
    gemm_tf32_kernel<<<gD, 256>>>(ff, W2, b2, x1, out, M_, D_, 4 * D_, 0);
}

// round 5
// speedup vs baseline: 1.9289x; 1.3178x over previous
#include <cuda_runtime.h>
#include <math.h>
#include <stdint.h>

static constexpr int B_ = 4, T_ = 2048, D_ = 1024, H_ = 16, HD_ = 64;
static constexpr int M_ = B_ * T_;   // 8192 rows

// ---- scratch (static; no allocation) ----
__device__ float g_h[M_ * D_];
__device__ float g_q[M_ * D_];
__device__ float g_k[M_ * D_];
__device__ float g_v[M_ * D_];
__device__ float g_attn[M_ * D_];
__device__ float g_x1[M_ * D_];
__device__ float g_ff[M_ * 4 * D_];
// pre-rounded (tf32) weights
__device__ float g_wq[D_ * D_];
__device__ float g_wk[D_ * D_];
__device__ float g_wv[D_ * D_];
__device__ float g_wo[D_ * D_];
__device__ float g_w1[D_ * 4 * D_];
__device__ float g_w2[4 * D_ * D_];

// ======================= helpers =======================
__device__ __forceinline__ float tf32r(float x) {
    uint32_t u;
    asm("cvt.rna.tf32.f32 %0, %1;" : "=r"(u) : "f"(x));
    return __uint_as_float(u);
}
__device__ __forceinline__ uint32_t smem_u32(const void* p) {
    uint32_t a;
    asm("{ .reg .u64 t; cvta.to.shared.u64 t, %1; cvt.u32.u64 %0, t; }" : "=r"(a) : "l"(p));
    return a;
}
__device__ __forceinline__ void cp16(uint32_t dst, const void* src) {
    asm volatile("cp.async.cg.shared.global [%0], [%1], 16;" :: "r"(dst), "l"(src));
}
__device__ __forceinline__ void cp_commit() {
    asm volatile("cp.async.commit_group;" ::: "memory");
}
__device__ __forceinline__ void cp_wait1() {
    asm volatile("cp.async.wait_group 1;" ::: "memory");
}
__device__ __forceinline__ uint32_t lds32(uint32_t a) {
    uint32_t v;
    asm volatile("ld.shared.b32 %0, [%1];" : "=r"(v) : "r"(a));
    return v;
}
__device__ __forceinline__ void mma_tf32(float* d, const uint32_t* a, const uint32_t* b) {
    asm volatile(
        "mma.sync.aligned.m16n8k8.row.col.f32.tf32.tf32.f32 "
        "{%0,%1,%2,%3}, {%4,%5,%6,%7}, {%8,%9}, {%0,%1,%2,%3};"
        : "+f"(d[0]), "+f"(d[1]), "+f"(d[2]), "+f"(d[3])
        : "r"(a[0]), "r"(a[1]), "r"(a[2]), "r"(a[3]), "r"(b[0]), "r"(b[1]));
}
__device__ __forceinline__ float gelu_f(float x) {
    float u = 0.7978845608028654f * (x + 0.044715f * x * x * x);
    return 0.5f * x * (1.f + tanhf(u));
}

// =============== weight tf32 pre-round ===============
__global__ __launch_bounds__(256) void wround_kernel(
    const float* __restrict__ in, float* __restrict__ out)
{
    int i = (blockIdx.x * 256 + threadIdx.x) * 4;
    float4 v = *(const float4*)(in + i);
    v.x = tf32r(v.x); v.y = tf32r(v.y); v.z = tf32r(v.z); v.w = tf32r(v.w);
    *(float4*)(out + i) = v;
}

// ======================= LayerNorm (tf32-rounded output) =================
__global__ __launch_bounds__(256) void ln_kernel(
    const float* __restrict__ x, const float* __restrict__ gamma,
    const float* __restrict__ beta, float* __restrict__ out)
{
    int row = blockIdx.x;
    const float* xr = x + (size_t)row * D_;
    float* orow = out + (size_t)row * D_;
    int t = threadIdx.x;
    float v[4];
    float s = 0.f, s2 = 0.f;
#pragma unroll
    for (int i = 0; i < 4; i++) {
        float val = xr[t + i * 256];
        v[i] = val; s += val; s2 += val * val;
    }
#pragma unroll
    for (int o = 16; o; o >>= 1) {
        s  += __shfl_xor_sync(0xffffffffu, s, o);
        s2 += __shfl_xor_sync(0xffffffffu, s2, o);
    }
    __shared__ float red[16];
    if ((t & 31) == 0) { red[t >> 5] = s; red[8 + (t >> 5)] = s2; }
    __syncthreads();
    float ts = 0.f, ts2 = 0.f;
#pragma unroll
    for (int w = 0; w < 8; w++) { ts += red[w]; ts2 += red[8 + w]; }
    float mean = ts * (1.f / D_);
    float var  = ts2 * (1.f / D_) - mean * mean;
    float inv  = rsqrtf(var + 1e-5f);
#pragma unroll
    for (int i = 0; i < 4; i++) {
        int c = t + i * 256;
        orow[c] = tf32r(gamma[c] * (v[i] - mean) * inv + beta[c]);
    }
}

// ======================= pipelined tf32 mma.sync GEMM ====================
// C[M,N] = A@W (+bias)(+resid)(gelu?)(tf32-round-out?)
// 128x128 tile, BK=32, 256 threads (8 warps: 4M x 2N), 3-stage cp.async.
// A smem: [m][k] 32 floats/row, 16B-chunk XOR swizzle (chunk ^= m&7).
// B smem: [k][n] stride 136 floats (pad 4) -> conflict-free frag loads.
static constexpr int AS_BYTES = 128 * 32 * 4;     // 16384
static constexpr int BS_BYTES = 32 * 136 * 4;     // 17408
static constexpr int STG_BYTES = AS_BYTES + BS_BYTES;
static constexpr int GEMM_SMEM = 3 * STG_BYTES;   // 101376

__global__ __launch_bounds__(256) void gemm_mma_kernel(
    const float* __restrict__ A, const float* __restrict__ W,
    const float* __restrict__ bias, const float* __restrict__ resid,
    float* __restrict__ C, int M, int N, int K, int act, int round_out)
{
    extern __shared__ char smem[];
    uint32_t sb = smem_u32(smem);
    int tid = threadIdx.x;
    int warp = tid >> 5, lane = tid & 31;
    int wm = warp & 3, wn = warp >> 2;
    int gr = lane >> 2, tig = lane & 3;
    int bm = blockIdx.y * 128;
    int bn = blockIdx.x * 128;

    // ---- loader setup ----
    int am = tid >> 1;                      // A row 0..127
    const float* Ag = A + (size_t)(bm + am) * K + (tid & 1) * 16;
    uint32_t a_st[4];
#pragma unroll
    for (int j = 0; j < 4; j++) {
        int chunk = (tid & 1) * 4 + j;
        a_st[j] = (uint32_t)(am * 128 + ((chunk ^ (am & 7)) << 4));
    }
    int bk = tid >> 3;                      // B k-row 0..31
    const float* Wg = W + (size_t)bk * N + bn + (tid & 7) * 16;
    uint32_t b_st = (uint32_t)(bk * 544 + (tid & 7) * 64);

    // ---- mma fragment address bases ----
    uint32_t preA[2];
#pragma unroll
    for (int i = 0; i < 2; i++)
        preA[i] = sb + (uint32_t)((wm * 32 + i * 16 + gr) * 128 + tig * 4);
    uint32_t preB = sb + (uint32_t)(AS_BYTES + tig * 544 + (wn * 64 + gr) * 4);

    float acc[2][8][4];
#pragma unroll
    for (int i = 0; i < 2; i++)
#pragma unroll
        for (int j = 0; j < 8; j++)
#pragma unroll
            for (int c = 0; c < 4; c++) acc[i][j][c] = 0.f;

    int NC = K >> 5;

    // prologue: stages 0,1
#pragma unroll
    for (int st = 0; st < 2; st++) {
        uint32_t base = sb + st * STG_BYTES;
        const float* ap = Ag + st * 32;
        const float* wp = Wg + (size_t)st * 32 * N;
#pragma unroll
        for (int j = 0; j < 4; j++) cp16(base + a_st[j], ap + j * 4);
#pragma unroll
        for (int j = 0; j < 4; j++) cp16(base + AS_BYTES + b_st + j * 16, wp + j * 4);
        cp_commit();
    }

    int slot = 0, nslot = 2;
    for (int c = 0; c < NC; c++) {
        cp_wait1();
        __syncthreads();

        if (c + 2 < NC) {
            uint32_t base = sb + nslot * STG_BYTES;
            const float* ap = Ag + (c + 2) * 32;
            const float* wp = Wg + (size_t)(c + 2) * 32 * N;
#pragma unroll
            for (int j = 0; j < 4; j++) cp16(base + a_st[j], ap + j * 4);
#pragma unroll
            for (int j = 0; j < 4; j++) cp16(base + AS_BYTES + b_st + j * 16, wp + j * 4);
        }
        cp_commit();

        uint32_t soff = (uint32_t)(slot * STG_BYTES);
#pragma unroll
        for (int s = 0; s < 4; s++) {
            uint32_t a[2][4];
#pragma unroll
            for (int i = 0; i < 2; i++) {
                uint32_t ad = preA[i] + soff + (uint32_t)(((2 * s) ^ gr) << 4);
                a[i][0] = lds32(ad);
                a[i][1] = lds32(ad + 1024);
                a[i][2] = lds32(ad ^ 16);
                a[i][3] = lds32((ad + 1024) ^ 16);
            }
#pragma unroll
            for (int j = 0; j < 8; j++) {
                uint32_t bd = preB + soff + (uint32_t)(s * 4352 + j * 32);
                uint32_t b[2];
                b[0] = lds32(bd);
                b[1] = lds32(bd + 2176);
                mma_tf32(acc[0][j], a[0], b);
                mma_tf32(acc[1][j], a[1], b);
            }
        }
        slot = slot + 1; if (slot == 3) slot = 0;
        nslot = nslot + 1; if (nslot == 3) nslot = 0;
    }

    // ---- epilogue ----
#pragma unroll
    for (int i = 0; i < 2; i++) {
#pragma unroll
        for (int j = 0; j < 8; j++) {
            int row0 = bm + wm * 32 + i * 16 + gr;
            int col  = bn + wn * 64 + j * 8 + tig * 2;
            float b0 = bias ? bias[col]     : 0.f;
            float b1 = bias ? bias[col + 1] : 0.f;
#pragma unroll
            for (int hh = 0; hh < 2; hh++) {
                int r = row0 + hh * 8;
                size_t off = (size_t)r * N + col;
                float v0 = acc[i][j][2 * hh + 0] + b0;
                float v1 = acc[i][j][2 * hh + 1] + b1;
                if (resid) { v0 += resid[off]; v1 += resid[off + 1]; }
                if (act) { v0 = gelu_f(v0); v1 = gelu_f(v1); }
                if (round_out) { v0 = tf32r(v0); v1 = tf32r(v1); }
                *(float2*)(C + off) = make_float2(v0, v1);
            }
        }
    }
}

// ======================= Causal flash attention ==========================
__global__ __launch_bounds__(256) void flash_kernel(
    const float* __restrict__ Qg, const float* __restrict__ Kg,
    const float* __restrict__ Vg, float* __restrict__ Og)
{
    extern __shared__ float sm[];
    float (*Qs)[68] = (float(*)[68])(sm);
    float (*Ks)[68] = (float(*)[68])(sm + 4352);
    float (*Vs)[68] = (float(*)[68])(sm + 2 * 4352);
    float (*PT)[68] = (float(*)[68])(sm + 3 * 4352);
    float (*Ss)[68] = (float(*)[68])(sm + 4 * 4352);
    float* m_s     = sm + 5 * 4352;
    float* l_s     = m_s + 64;
    float* alpha_s = l_s + 64;

    int qt = blockIdx.x, bh = blockIdx.y;
    int b = bh >> 4, h = bh & 15;
    int tid = threadIdx.x;
    int ty = tid >> 4, tx = tid & 15;
    const size_t base = (size_t)b * T_ * D_ + (size_t)h * HD_;

    int lr  = tid >> 2;
    int ldc = (tid & 3) * 16;
    {
        const float* qp = Qg + base + (size_t)(qt * 64 + lr) * D_ + ldc;
#pragma unroll
        for (int c = 0; c < 16; c += 4) {
            float4 v = *(const float4*)(qp + c);
            Qs[ldc + c + 0][lr] = v.x; Qs[ldc + c + 1][lr] = v.y;
            Qs[ldc + c + 2][lr] = v.z; Qs[ldc + c + 3][lr] = v.w;
        }
    }
    if (tid < 64) { m_s[tid] = -INFINITY; l_s[tid] = 0.f; }

    float acc[4][4];
#pragma unroll
    for (int i = 0; i < 4; i++)
#pragma unroll
        for (int j = 0; j < 4; j++) acc[i][j] = 0.f;

    for (int kt = 0; kt <= qt; kt++) {
        __syncthreads();
        {
            const float* kp = Kg + base + (size_t)(kt * 64 + lr) * D_ + ldc;
            const float* vp = Vg + base + (size_t)(kt * 64 + lr) * D_ + ldc;
#pragma unroll
            for (int c = 0; c < 16; c += 4) {
                float4 kv = *(const float4*)(kp + c);
                Ks[ldc + c + 0][lr] = kv.x; Ks[ldc + c + 1][lr] = kv.y;
                Ks[ldc + c + 2][lr] = kv.z; Ks[ldc + c + 3][lr] = kv.w;
                float4 vv = *(const float4*)(vp + c);
                *(float4*)&Vs[lr][ldc + c] = vv;
            }
        }
        __syncthreads();

        float sa[4][4];
#pragma unroll
        for (int i = 0; i < 4; i++)
#pragma unroll
            for (int j = 0; j < 4; j++) sa[i][j] = 0.f;
#pragma unroll 8
        for (int kk = 0; kk < 64; kk++) {
            float4 av = *(const float4*)&Qs[kk][ty * 4];
            float4 bv = *(const float4*)&Ks[kk][tx * 4];
            float aa[4] = {av.x, av.y, av.z, av.w};
            float bb[4] = {bv.x, bv.y, bv.z, bv.w};
#pragma unroll
            for (int i = 0; i < 4; i++)
#pragma unroll
                for (int j = 0; j < 4; j++)
                    sa[i][j] = fmaf(aa[i], bb[j], sa[i][j]);
        }
#pragma unroll
        for (int i = 0; i < 4; i++) {
            float4 s4 = make_float4(sa[i][0] * 0.125f, sa[i][1] * 0.125f,
                                    sa[i][2] * 0.125f, sa[i][3] * 0.125f);
            *(float4*)&Ss[ty * 4 + i][tx * 4] = s4;
        }
        __syncthreads();

        {
            int row = tid >> 2, sub = tid & 3;
            int jb = sub * 16;
            bool diag = (kt == qt);
            float sv[16];
            float mloc = -INFINITY;
#pragma unroll
            for (int jj = 0; jj < 16; jj++) {
                float s = Ss[row][jb + jj];
                if (diag && (jb + jj) > row) s = -INFINITY;
                sv[jj] = s;
                mloc = fmaxf(mloc, s);
            }
            mloc = fmaxf(mloc, __shfl_xor_sync(0xffffffffu, mloc, 1));
            mloc = fmaxf(mloc, __shfl_xor_sync(0xffffffffu, mloc, 2));
            float m_old = m_s[row];
            float m_new = fmaxf(m_old, mloc);
            float ps = 0.f;
#pragma unroll
            for (int jj = 0; jj < 16; jj++) {
                float p = (sv[jj] == -INFINITY) ? 0.f : __expf(sv[jj] - m_new);
                PT[jb + jj][row] = p;
                ps += p;
            }
            ps += __shfl_xor_sync(0xffffffffu, ps, 1);
            ps += __shfl_xor_sync(0xffffffffu, ps, 2);
            if (sub == 0) {
                float alpha = (m_old == -INFINITY) ? 0.f : __expf(m_old - m_new);
                alpha_s[row] = alpha;
                l_s[row] = l_s[row] * alpha + ps;
                m_s[row] = m_new;
            }
        }
        __syncthreads();

        float al[4];
#pragma unroll
        for (int i = 0; i < 4; i++) al[i] = alpha_s[ty * 4 + i];
#pragma unroll
        for (int i = 0; i < 4; i++)
#pragma unroll
            for (int j = 0; j < 4; j++) acc[i][j] *= al[i];
#pragma unroll 8
        for (int j = 0; j < 64; j++) {
            float4 pv = *(const float4*)&PT[j][ty * 4];
            float4 vv = *(const float4*)&Vs[j][tx * 4];
            float pp[4] = {pv.x, pv.y, pv.z, pv.w};
            float bb[4] = {vv.x, vv.y, vv.z, vv.w};
#pragma unroll
            for (int i = 0; i < 4; i++)
#pragma unroll
                for (int jj = 0; jj < 4; jj++)
                    acc[i][jj] = fmaf(pp[i], bb[jj], acc[i][jj]);
        }
    }
    __syncthreads();

    float inv[4];
#pragma unroll
    for (int i = 0; i < 4; i++) inv[i] = 1.f / l_s[ty * 4 + i];
#pragma unroll
    for (int i = 0; i < 4; i++) {
        float* op = Og + base + (size_t)(qt * 64 + ty * 4 + i) * D_ + tx * 4;
        // tf32-round: attn feeds the Wo GEMM via cp.async
        float4 o4 = make_float4(tf32r(acc[i][0] * inv[i]), tf32r(acc[i][1] * inv[i]),
                                tf32r(acc[i][2] * inv[i]), tf32r(acc[i][3] * inv[i]));
        *(float4*)op = o4;
    }
}

// ======================= launch ==========================================
extern "C" void kernel_launch(void* const* d_in, const int* in_sizes, int n_in,
                              void* d_out, int out_size)
{
    const float* x      = (const float*)d_in[0];
    const float* Wq     = (const float*)d_in[1];
    const float* Wk     = (const float*)d_in[2];
    const float* Wv     = (const float*)d_in[3];
    const float* Wo     = (const float*)d_in[4];
    const float* bo     = (const float*)d_in[5];
    const float* W1     = (const float*)d_in[6];
    const float* b1     = (const float*)d_in[7];
    const float* W2     = (const float*)d_in[8];
    const float* b2     = (const float*)d_in[9];
    const float* gamma1 = (const float*)d_in[10];
    const float* beta1  = (const float*)d_in[11];
    const float* gamma2 = (const float*)d_in[12];
    const float* beta2  = (const float*)d_in[13];
    float* out = (float*)d_out;

    float *h, *q, *k, *v, *attn, *x1, *ff;
    float *wq, *wk, *wv, *wo, *w1, *w2;
    cudaGetSymbolAddress((void**)&h,    g_h);
    cudaGetSymbolAddress((void**)&q,    g_q);
    cudaGetSymbolAddress((void**)&k,    g_k);
    cudaGetSymbolAddress((void**)&v,    g_v);
    cudaGetSymbolAddress((void**)&attn, g_attn);
    cudaGetSymbolAddress((void**)&x1,   g_x1);
    cudaGetSymbolAddress((void**)&ff,   g_ff);
    cudaGetSymbolAddress((void**)&wq,   g_wq);
    cudaGetSymbolAddress((void**)&wk,   g_wk);
    cudaGetSymbolAddress((void**)&wv,   g_wv);
    cudaGetSymbolAddress((void**)&wo,   g_wo);
    cudaGetSymbolAddress((void**)&w1,   g_w1);
    cudaGetSymbolAddress((void**)&w2,   g_w2);

    cudaFuncSetAttribute(gemm_mma_kernel, cudaFuncAttributeMaxDynamicSharedMemorySize, GEMM_SMEM);

    // pre-round weights to tf32 grid
    wround_kernel<<<D_ * D_ / 1024, 256>>>(Wq, wq);
    wround_kernel<<<D_ * D_ / 1024, 256>>>(Wk, wk);
    wround_kernel<<<D_ * D_ / 1024, 256>>>(Wv, wv);
    wround_kernel<<<D_ * D_ / 1024, 256>>>(Wo, wo);
    wround_kernel<<<D_ * 4 * D_ / 1024, 256>>>(W1, w1);
    wround_kernel<<<4 * D_ * D_ / 1024, 256>>>(W2, w2);

    // LN1 (tf32-rounded output)
    ln_kernel<<<M_, 256>>>(x, gamma1, beta1, h);

    // QKV projections
    dim3 gD(D_ / 128, M_ / 128);
    gemm_mma_kernel<<<gD, 256, GEMM_SMEM>>>(h, wq, nullptr, nullptr, q, M_, D_, D_, 0, 0);
    gemm_mma_kernel<<<gD, 256, GEMM_SMEM>>>(h, wk, nullptr, nullptr, k, M_, D_, D_, 0, 0);
    gemm_mma_kernel<<<gD, 256, GEMM_SMEM>>>(h, wv, nullptr, nullptr, v, M_, D_, D_, 0, 0);

    // causal attention
    const int FLASH_SMEM = (5 * 4352 + 192) * (int)sizeof(float);
    cudaFuncSetAttribute(flash_kernel, cudaFuncAttributeMaxDynamicSharedMemorySize, FLASH_SMEM);
    dim3 gf(T_ / 64, B_ * H_);
    flash_kernel<<<gf, 256, FLASH_SMEM>>>(q, k, v, attn);

    // output projection + residual
    gemm_mma_kernel<<<gD, 256, GEMM_SMEM>>>(attn, wo, bo, x, x1, M_, D_, D_, 0, 0);

    // LN2
    ln_kernel<<<M_, 256>>>(x1, gamma2, beta2, h);

    // FFN (W1 output rounded: it feeds the W2 GEMM)
    dim3 gU(4 * D_ / 128, M_ / 128);
    gemm_mma_kernel<<<gU, 256, GEMM_SMEM>>>(h, w1, b1, nullptr, ff, M_, 4 * D_, D_, 1, 1);
    gemm_mma_kernel<<<gD, 256, GEMM_SMEM>>>(ff, w2, b2, x1, out, M_, D_, 4 * D_, 0, 0);
}

// round 6
// speedup vs baseline: 2.3651x; 1.2262x over previous
#include <cuda_runtime.h>
#include <math.h>
#include <stdint.h>

static constexpr int B_ = 4, T_ = 2048, D_ = 1024, H_ = 16, HD_ = 64;
static constexpr int M_ = B_ * T_;   // 8192 rows

// ---- scratch (static; no allocation) ----
__device__ float g_h[M_ * D_];
__device__ float g_q[M_ * D_];
__device__ float g_k[M_ * D_];
__device__ float g_v[M_ * D_];
__device__ float g_attn[M_ * D_];
__device__ float g_x1[M_ * D_];
__device__ float g_ff[M_ * 4 * D_];
// pre-rounded (tf32) weights
__device__ float g_wq[D_ * D_];
__device__ float g_wk[D_ * D_];
__device__ float g_wv[D_ * D_];
__device__ float g_wo[D_ * D_];
__device__ float g_w1[D_ * 4 * D_];
__device__ float g_w2[4 * D_ * D_];

// ======================= helpers =======================
__device__ __forceinline__ float tf32r(float x) {
    uint32_t u;
    asm("cvt.rna.tf32.f32 %0, %1;" : "=r"(u) : "f"(x));
    return __uint_as_float(u);
}
__device__ __forceinline__ uint32_t smem_u32(const void* p) {
    uint32_t a;
    asm("{ .reg .u64 t; cvta.to.shared.u64 t, %1; cvt.u32.u64 %0, t; }" : "=r"(a) : "l"(p));
    return a;
}
__device__ __forceinline__ void cp16(uint32_t dst, const void* src) {
    asm volatile("cp.async.cg.shared.global [%0], [%1], 16;" :: "r"(dst), "l"(src));
}
__device__ __forceinline__ void cp_commit() {
    asm volatile("cp.async.commit_group;" ::: "memory");
}
__device__ __forceinline__ void cp_wait1() {
    asm volatile("cp.async.wait_group 1;" ::: "memory");
}
__device__ __forceinline__ uint32_t lds32(uint32_t a) {
    uint32_t v;
    asm volatile("ld.shared.b32 %0, [%1];" : "=r"(v) : "r"(a));
    return v;
}
__device__ __forceinline__ void mma_tf32(float* d, const uint32_t* a, const uint32_t* b) {
    asm volatile(
        "mma.sync.aligned.m16n8k8.row.col.f32.tf32.tf32.f32 "
        "{%0,%1,%2,%3}, {%4,%5,%6,%7}, {%8,%9}, {%0,%1,%2,%3};"
        : "+f"(d[0]), "+f"(d[1]), "+f"(d[2]), "+f"(d[3])
        : "r"(a[0]), "r"(a[1]), "r"(a[2]), "r"(a[3]), "r"(b[0]), "r"(b[1]));
}
__device__ __forceinline__ float gelu_f(float x) {
    float u = 0.7978845608028654f * (x + 0.044715f * x * x * x);
    return 0.5f * x * (1.f + tanhf(u));
}

// =============== weight tf32 pre-round ===============
__global__ __launch_bounds__(256) void wround_kernel(
    const float* __restrict__ in, float* __restrict__ out)
{
    int i = (blockIdx.x * 256 + threadIdx.x) * 4;
    float4 v = *(const float4*)(in + i);
    v.x = tf32r(v.x); v.y = tf32r(v.y); v.z = tf32r(v.z); v.w = tf32r(v.w);
    *(float4*)(out + i) = v;
}

// ======================= LayerNorm (tf32-rounded output) =================
__global__ __launch_bounds__(256) void ln_kernel(
    const float* __restrict__ x, const float* __restrict__ gamma,
    const float* __restrict__ beta, float* __restrict__ out)
{
    int row = blockIdx.x;
    const float* xr = x + (size_t)row * D_;
    float* orow = out + (size_t)row * D_;
    int t = threadIdx.x;
    float v[4];
    float s = 0.f, s2 = 0.f;
#pragma unroll
    for (int i = 0; i < 4; i++) {
        float val = xr[t + i * 256];
        v[i] = val; s += val; s2 += val * val;
    }
#pragma unroll
    for (int o = 16; o; o >>= 1) {
        s  += __shfl_xor_sync(0xffffffffu, s, o);
        s2 += __shfl_xor_sync(0xffffffffu, s2, o);
    }
    __shared__ float red[16];
    if ((t & 31) == 0) { red[t >> 5] = s; red[8 + (t >> 5)] = s2; }
    __syncthreads();
    float ts = 0.f, ts2 = 0.f;
#pragma unroll
    for (int w = 0; w < 8; w++) { ts += red[w]; ts2 += red[8 + w]; }
    float mean = ts * (1.f / D_);
    float var  = ts2 * (1.f / D_) - mean * mean;
    float inv  = rsqrtf(var + 1e-5f);
#pragma unroll
    for (int i = 0; i < 4; i++) {
        int c = t + i * 256;
        orow[c] = tf32r(gamma[c] * (v[i] - mean) * inv + beta[c]);
    }
}

// ======================= pipelined tf32 mma.sync GEMM ====================
static constexpr int AS_BYTES = 128 * 32 * 4;     // 16384
static constexpr int BS_BYTES = 32 * 136 * 4;     // 17408
static constexpr int STG_BYTES = AS_BYTES + BS_BYTES;
static constexpr int GEMM_SMEM = 3 * STG_BYTES;   // 101376

__global__ __launch_bounds__(256) void gemm_mma_kernel(
    const float* __restrict__ A, const float* __restrict__ W,
    const float* __restrict__ bias, const float* __restrict__ resid,
    float* __restrict__ C, int M, int N, int K, int act, int round_out)
{
    extern __shared__ char smem[];
    uint32_t sb = smem_u32(smem);
    int tid = threadIdx.x;
    int warp = tid >> 5, lane = tid & 31;
    int wm = warp & 3, wn = warp >> 2;
    int gr = lane >> 2, tig = lane & 3;
    int bm = blockIdx.y * 128;
    int bn = blockIdx.x * 128;

    int am = tid >> 1;
    const float* Ag = A + (size_t)(bm + am) * K + (tid & 1) * 16;
    uint32_t a_st[4];
#pragma unroll
    for (int j = 0; j < 4; j++) {
        int chunk = (tid & 1) * 4 + j;
        a_st[j] = (uint32_t)(am * 128 + ((chunk ^ (am & 7)) << 4));
    }
    int bk = tid >> 3;
    const float* Wg = W + (size_t)bk * N + bn + (tid & 7) * 16;
    uint32_t b_st = (uint32_t)(bk * 544 + (tid & 7) * 64);

    uint32_t preA[2];
#pragma unroll
    for (int i = 0; i < 2; i++)
        preA[i] = sb + (uint32_t)((wm * 32 + i * 16 + gr) * 128 + tig * 4);
    uint32_t preB = sb + (uint32_t)(AS_BYTES + tig * 544 + (wn * 64 + gr) * 4);

    float acc[2][8][4];
#pragma unroll
    for (int i = 0; i < 2; i++)
#pragma unroll
        for (int j = 0; j < 8; j++)
#pragma unroll
            for (int c = 0; c < 4; c++) acc[i][j][c] = 0.f;

    int NC = K >> 5;

#pragma unroll
    for (int st = 0; st < 2; st++) {
        uint32_t base = sb + st * STG_BYTES;
        const float* ap = Ag + st * 32;
        const float* wp = Wg + (size_t)st * 32 * N;
#pragma unroll
        for (int j = 0; j < 4; j++) cp16(base + a_st[j], ap + j * 4);
#pragma unroll
        for (int j = 0; j < 4; j++) cp16(base + AS_BYTES + b_st + j * 16, wp + j * 4);
        cp_commit();
    }

    int slot = 0, nslot = 2;
    for (int c = 0; c < NC; c++) {
        cp_wait1();
        __syncthreads();

        if (c + 2 < NC) {
            uint32_t base = sb + nslot * STG_BYTES;
            const float* ap = Ag + (c + 2) * 32;
            const float* wp = Wg + (size_t)(c + 2) * 32 * N;
#pragma unroll
            for (int j = 0; j < 4; j++) cp16(base + a_st[j], ap + j * 4);
#pragma unroll
            for (int j = 0; j < 4; j++) cp16(base + AS_BYTES + b_st + j * 16, wp + j * 4);
        }
        cp_commit();

        uint32_t soff = (uint32_t)(slot * STG_BYTES);
#pragma unroll
        for (int s = 0; s < 4; s++) {
            uint32_t a[2][4];
#pragma unroll
            for (int i = 0; i < 2; i++) {
                uint32_t ad = preA[i] + soff + (uint32_t)(((2 * s) ^ gr) << 4);
                a[i][0] = lds32(ad);
                a[i][1] = lds32(ad + 1024);
                a[i][2] = lds32(ad ^ 16);
                a[i][3] = lds32((ad + 1024) ^ 16);
            }
#pragma unroll
            for (int j = 0; j < 8; j++) {
                uint32_t bd = preB + soff + (uint32_t)(s * 4352 + j * 32);
                uint32_t b[2];
                b[0] = lds32(bd);
                b[1] = lds32(bd + 2176);
                mma_tf32(acc[0][j], a[0], b);
                mma_tf32(acc[1][j], a[1], b);
            }
        }
        slot = slot + 1; if (slot == 3) slot = 0;
        nslot = nslot + 1; if (nslot == 3) nslot = 0;
    }

#pragma unroll
    for (int i = 0; i < 2; i++) {
#pragma unroll
        for (int j = 0; j < 8; j++) {
            int row0 = bm + wm * 32 + i * 16 + gr;
            int col  = bn + wn * 64 + j * 8 + tig * 2;
            float b0 = bias ? bias[col]     : 0.f;
            float b1 = bias ? bias[col + 1] : 0.f;
#pragma unroll
            for (int hh = 0; hh < 2; hh++) {
                int r = row0 + hh * 8;
                size_t off = (size_t)r * N + col;
                float v0 = acc[i][j][2 * hh + 0] + b0;
                float v1 = acc[i][j][2 * hh + 1] + b1;
                if (resid) { v0 += resid[off]; v1 += resid[off + 1]; }
                if (act) { v0 = gelu_f(v0); v1 = gelu_f(v1); }
                if (round_out) { v0 = tf32r(v0); v1 = tf32r(v1); }
                *(float2*)(C + off) = make_float2(v0, v1);
            }
        }
    }
}

// ======================= tensor-core causal flash attention ==============
// 64x64 tiles, 256 threads (8 warps: 4M x 2N), m16n8k8 tf32 for S and PV.
// Qs/Ss stride 68 ([row][col]); Kt/Vs stride 72 ([k][n] for B frags).
static constexpr int FL_QS = 0;                  // 64*68
static constexpr int FL_KT = 64 * 68;            // 64*72  [d][j]
static constexpr int FL_VS = FL_KT + 64 * 72;    // 64*72  [j][d]
static constexpr int FL_SS = FL_VS + 64 * 72;    // 64*68  [q][j]
static constexpr int FL_ST = FL_SS + 64 * 68;    // stats: m, l, alpha (64 each)
static constexpr int FLASH_SMEM = (FL_ST + 192) * 4;   // 72448 B

__global__ __launch_bounds__(256, 2) void flash_kernel(
    const float* __restrict__ Qg, const float* __restrict__ Kg,
    const float* __restrict__ Vg, float* __restrict__ Og)
{
    extern __shared__ float sm[];
    float* Qs = sm + FL_QS;
    float* Kt = sm + FL_KT;
    float* Vs = sm + FL_VS;
    float* Ss = sm + FL_SS;
    float* m_s = sm + FL_ST;
    float* l_s = m_s + 64;
    float* alpha_s = l_s + 64;

    int qt = blockIdx.x, bh = blockIdx.y;
    int b = bh >> 4, h = bh & 15;
    int tid = threadIdx.x;
    int warp = tid >> 5, lane = tid & 31;
    int wm = warp & 3, wn = warp >> 2;
    int gr = lane >> 2, tig = lane & 3;
    int m0 = wm * 16;
    const size_t base = (size_t)b * T_ * D_ + (size_t)h * HD_;

    int lr  = tid >> 2;          // 0..63
    int ldc = (tid & 3) * 16;    // 0,16,32,48

    // load Q tile (tf32-rounded)
    {
        const float* qp = Qg + base + (size_t)(qt * 64 + lr) * D_ + ldc;
#pragma unroll
        for (int c = 0; c < 16; c += 4) {
            float4 v = *(const float4*)(qp + c);
            *(float4*)&Qs[lr * 68 + ldc + c] =
                make_float4(tf32r(v.x), tf32r(v.y), tf32r(v.z), tf32r(v.w));
        }
    }
    if (tid < 64) { m_s[tid] = -INFINITY; l_s[tid] = 0.f; }

    float oacc[4][4];
#pragma unroll
    for (int j = 0; j < 4; j++)
#pragma unroll
        for (int c = 0; c < 4; c++) oacc[j][c] = 0.f;

    for (int kt = 0; kt <= qt; kt++) {
        __syncthreads();   // protect Kt/Vs/Ss from previous iteration readers
        {
            const float* kp = Kg + base + (size_t)(kt * 64 + lr) * D_ + ldc;
            const float* vp = Vg + base + (size_t)(kt * 64 + lr) * D_ + ldc;
#pragma unroll
            for (int c = 0; c < 16; c += 4) {
                float4 kv = *(const float4*)(kp + c);
                Kt[(ldc + c + 0) * 72 + lr] = tf32r(kv.x);
                Kt[(ldc + c + 1) * 72 + lr] = tf32r(kv.y);
                Kt[(ldc + c + 2) * 72 + lr] = tf32r(kv.z);
                Kt[(ldc + c + 3) * 72 + lr] = tf32r(kv.w);
                float4 vv = *(const float4*)(vp + c);
                *(float4*)&Vs[lr * 72 + ldc + c] =
                    make_float4(tf32r(vv.x), tf32r(vv.y), tf32r(vv.z), tf32r(vv.w));
            }
        }
        __syncthreads();

        // ---- S = Q @ K^T (tensor cores) ----
        float sa[4][4];
#pragma unroll
        for (int j = 0; j < 4; j++)
#pragma unroll
            for (int c = 0; c < 4; c++) sa[j][c] = 0.f;
#pragma unroll
        for (int s = 0; s < 8; s++) {
            int kb = 8 * s;
            uint32_t a[4];
            a[0] = __float_as_uint(Qs[(m0 + gr) * 68 + kb + tig]);
            a[1] = __float_as_uint(Qs[(m0 + gr + 8) * 68 + kb + tig]);
            a[2] = __float_as_uint(Qs[(m0 + gr) * 68 + kb + tig + 4]);
            a[3] = __float_as_uint(Qs[(m0 + gr + 8) * 68 + kb + tig + 4]);
#pragma unroll
            for (int j = 0; j < 4; j++) {
                int n = wn * 32 + j * 8 + gr;
                uint32_t bb[2];
                bb[0] = __float_as_uint(Kt[(kb + tig) * 72 + n]);
                bb[1] = __float_as_uint(Kt[(kb + tig + 4) * 72 + n]);
                mma_tf32(sa[j], a, bb);
            }
        }
        // write scaled S
#pragma unroll
        for (int j = 0; j < 4; j++) {
            int col = wn * 32 + j * 8 + 2 * tig;
            *(float2*)&Ss[(m0 + gr) * 68 + col] =
                make_float2(sa[j][0] * 0.125f, sa[j][1] * 0.125f);
            *(float2*)&Ss[(m0 + gr + 8) * 68 + col] =
                make_float2(sa[j][2] * 0.125f, sa[j][3] * 0.125f);
        }
        __syncthreads();

        // ---- online softmax (in place, P tf32-rounded) ----
        {
            int row = tid >> 2, sub = tid & 3;
            int jb = sub * 16;
            bool diag = (kt == qt);
            float sv[16];
            float mloc = -INFINITY;
#pragma unroll
            for (int jj = 0; jj < 16; jj++) {
                float s = Ss[row * 68 + jb + jj];
                if (diag && (jb + jj) > row) s = -INFINITY;
                sv[jj] = s;
                mloc = fmaxf(mloc, s);
            }
            mloc = fmaxf(mloc, __shfl_xor_sync(0xffffffffu, mloc, 1));
            mloc = fmaxf(mloc, __shfl_xor_sync(0xffffffffu, mloc, 2));
            float m_old = m_s[row];
            float m_new = fmaxf(m_old, mloc);
            float ps = 0.f;
#pragma unroll
            for (int jj = 0; jj < 16; jj++) {
                float p = (sv[jj] == -INFINITY) ? 0.f : __expf(sv[jj] - m_new);
                Ss[row * 68 + jb + jj] = tf32r(p);
                ps += p;
            }
            ps += __shfl_xor_sync(0xffffffffu, ps, 1);
            ps += __shfl_xor_sync(0xffffffffu, ps, 2);
            if (sub == 0) {
                float alpha = (m_old == -INFINITY) ? 0.f : __expf(m_old - m_new);
                alpha_s[row] = alpha;
                l_s[row] = l_s[row] * alpha + ps;
                m_s[row] = m_new;
            }
        }
        __syncthreads();

        // ---- rescale + O += P @ V (tensor cores) ----
        float al0 = alpha_s[m0 + gr];
        float al1 = alpha_s[m0 + gr + 8];
#pragma unroll
        for (int j = 0; j < 4; j++) {
            oacc[j][0] *= al0; oacc[j][1] *= al0;
            oacc[j][2] *= al1; oacc[j][3] *= al1;
        }
#pragma unroll
        for (int s = 0; s < 8; s++) {
            int jb = 8 * s;
            uint32_t a[4];
            a[0] = __float_as_uint(Ss[(m0 + gr) * 68 + jb + tig]);
            a[1] = __float_as_uint(Ss[(m0 + gr + 8) * 68 + jb + tig]);
            a[2] = __float_as_uint(Ss[(m0 + gr) * 68 + jb + tig + 4]);
            a[3] = __float_as_uint(Ss[(m0 + gr + 8) * 68 + jb + tig + 4]);
#pragma unroll
            for (int j = 0; j < 4; j++) {
                int n = wn * 32 + j * 8 + gr;
                uint32_t bb[2];
                bb[0] = __float_as_uint(Vs[(jb + tig) * 72 + n]);
                bb[1] = __float_as_uint(Vs[(jb + tig + 4) * 72 + n]);
                mma_tf32(oacc[j], a, bb);
            }
        }
    }
    __syncthreads();

    float inv0 = 1.f / l_s[m0 + gr];
    float inv1 = 1.f / l_s[m0 + gr + 8];
#pragma unroll
    for (int j = 0; j < 4; j++) {
        int col = wn * 32 + j * 8 + 2 * tig;
        float* op0 = Og + base + (size_t)(qt * 64 + m0 + gr) * D_ + col;
        float* op1 = Og + base + (size_t)(qt * 64 + m0 + gr + 8) * D_ + col;
        // tf32-round: attn feeds the Wo GEMM
        *(float2*)op0 = make_float2(tf32r(oacc[j][0] * inv0), tf32r(oacc[j][1] * inv0));
        *(float2*)op1 = make_float2(tf32r(oacc[j][2] * inv1), tf32r(oacc[j][3] * inv1));
    }
}

// ======================= launch ==========================================
extern "C" void kernel_launch(void* const* d_in, const int* in_sizes, int n_in,
                              void* d_out, int out_size)
{
    const float* x      = (const float*)d_in[0];
    const float* Wq     = (const float*)d_in[1];
    const float* Wk     = (const float*)d_in[2];
    const float* Wv     = (const float*)d_in[3];
    const float* Wo     = (const float*)d_in[4];
    const float* bo     = (const float*)d_in[5];
    const float* W1     = (const float*)d_in[6];
    const float* b1     = (const float*)d_in[7];
    const float* W2     = (const float*)d_in[8];
    const float* b2     = (const float*)d_in[9];
    const float* gamma1 = (const float*)d_in[10];
    const float* beta1  = (const float*)d_in[11];
    const float* gamma2 = (const float*)d_in[12];
    const float* beta2  = (const float*)d_in[13];
    float* out = (float*)d_out;

    float *h, *q, *k, *v, *attn, *x1, *ff;
    float *wq, *wk, *wv, *wo, *w1, *w2;
    cudaGetSymbolAddress((void**)&h,    g_h);
    cudaGetSymbolAddress((void**)&q,    g_q);
    cudaGetSymbolAddress((void**)&k,    g_k);
    cudaGetSymbolAddress((void**)&v,    g_v);
    cudaGetSymbolAddress((void**)&attn, g_attn);
    cudaGetSymbolAddress((void**)&x1,   g_x1);
    cudaGetSymbolAddress((void**)&ff,   g_ff);
    cudaGetSymbolAddress((void**)&wq,   g_wq);
    cudaGetSymbolAddress((void**)&wk,   g_wk);
    cudaGetSymbolAddress((void**)&wv,   g_wv);
    cudaGetSymbolAddress((void**)&wo,   g_wo);
    cudaGetSymbolAddress((void**)&w1,   g_w1);
    cudaGetSymbolAddress((void**)&w2,   g_w2);

    cudaFuncSetAttribute(gemm_mma_kernel, cudaFuncAttributeMaxDynamicSharedMemorySize, GEMM_SMEM);
    cudaFuncSetAttribute(flash_kernel, cudaFuncAttributeMaxDynamicSharedMemorySize, FLASH_SMEM);

    // pre-round weights to tf32 grid
    wround_kernel<<<D_ * D_ / 1024, 256>>>(Wq, wq);
    wround_kernel<<<D_ * D_ / 1024, 256>>>(Wk, wk);
    wround_kernel<<<D_ * D_ / 1024, 256>>>(Wv, wv);
    wround_kernel<<<D_ * D_ / 1024, 256>>>(Wo, wo);
    wround_kernel<<<D_ * 4 * D_ / 1024, 256>>>(W1, w1);
    wround_kernel<<<4 * D_ * D_ / 1024, 256>>>(W2, w2);

    // LN1 (tf32-rounded output)
    ln_kernel<<<M_, 256>>>(x, gamma1, beta1, h);

    // QKV projections
    dim3 gD(D_ / 128, M_ / 128);
    gemm_mma_kernel<<<gD, 256, GEMM_SMEM>>>(h, wq, nullptr, nullptr, q, M_, D_, D_, 0, 0);
    gemm_mma_kernel<<<gD, 256, GEMM_SMEM>>>(h, wk, nullptr, nullptr, k, M_, D_, D_, 0, 0);
    gemm_mma_kernel<<<gD, 256, GEMM_SMEM>>>(h, wv, nullptr, nullptr, v, M_, D_, D_, 0, 0);

    // causal attention (tensor cores)
    dim3 gf(T_ / 64, B_ * H_);
    flash_kernel<<<gf, 256, FLASH_SMEM>>>(q, k, v, attn);

    // output projection + residual
    gemm_mma_kernel<<<gD, 256, GEMM_SMEM>>>(attn, wo, bo, x, x1, M_, D_, D_, 0, 0);

    // LN2
    ln_kernel<<<M_, 256>>>(x1, gamma2, beta2, h);

    // FFN (W1 output rounded: it feeds the W2 GEMM)
    dim3 gU(4 * D_ / 128, M_ / 128);
    gemm_mma_kernel<<<gU, 256, GEMM_SMEM>>>(h, w1, b1, nullptr, ff, M_, 4 * D_, D_, 1, 1);
    gemm_mma_kernel<<<gD, 256, GEMM_SMEM>>>(ff, w2, b2, x1, out, M_, D_, 4 * D_, 0, 0);
}